// round 17
// baseline (speedup 1.0000x reference)
#include <cuda_runtime.h>
#include <cstdint>

// VLAD pooling via warp-level bf16 MMA (mma.sync m16n8k16, base-target safe).
// x [32,4096,128] f32, centroids [64,128] f32 -> out [32, 8192] f32
//
// R17: 4-way interleaved MMA chains (B fragments for a jj-pair loaded up
//      front, 12 MMAs emitted round-robin across 4 accumulators -> RAW
//      spacing 4 instead of 1) + L2 prefetch of next x tile.
//      Otherwise identical to R16 (2 CTAs/SM, 64-pt tiles, fused finalize).

#define B_     32
#define N_     4096
#define D_     128
#define K_     64
#define ALPHA_ 100.0f
#define TILE_  64
#define NT_    2048          // 32 batches * 64 tiles
#define NCTA_  296
#define BASE_T 6
#define EXTRA_T 272          // NT_ - NCTA_*BASE_T (ctas 0..271 own 7 tiles)

#define XROW 272             // 128 bf16 = 256B, padded +16
#define AROW 144             // 64 bf16 = 128B, padded +16

#define SM_XHI 0             // [64][XROW]
#define SM_XLO 17408
#define SM_CHI 34816         // [64][XROW]
#define SM_CLO 52224
#define SM_AHI 69632         // [64][AROW]
#define SM_ALO 78848
#define SM_X2  88064         // 64 f32
#define SM_C2  88320         // 64 f32
#define SM_RED 88576         // float2 red[2][64]
#define SMEM_BYTES 89600

__device__ float g_vlad[B_ * K_ * D_];
__device__ float g_asum[B_ * K_];
__device__ int   g_done[B_];

__global__ void vlad_zero() {
    int i = blockIdx.x * blockDim.x + threadIdx.x;
    if (i < B_ * K_ * D_) g_vlad[i] = 0.f;
    if (i < B_ * K_) g_asum[i] = 0.f;
    if (i < B_) g_done[i] = 0;
}

// ---------------- helpers ---------------------------------------------------
__device__ __forceinline__ uint32_t smem_u32(const void* p) {
    uint32_t a;
    asm("{ .reg .u64 t; cvta.to.shared.u64 t, %1; cvt.u32.u64 %0, t; }" : "=r"(a) : "l"(p));
    return a;
}
__device__ __forceinline__ uint32_t pkbf(float lo, float hi) {
    uint32_t r;
    asm("cvt.rn.bf16x2.f32 %0, %1, %2;" : "=r"(r) : "f"(hi), "f"(lo));
    return r;
}
__device__ __forceinline__ void split2(float v0, float v1, uint32_t& hw, uint32_t& lw) {
    hw = pkbf(v0, v1);
    float h0 = __uint_as_float(hw << 16);
    float h1 = __uint_as_float(hw & 0xffff0000u);
    lw = pkbf(v0 - h0, v1 - h1);
}
__device__ __forceinline__ void ldm_x4(uint32_t addr, uint32_t* r) {
    asm volatile("ldmatrix.sync.aligned.m8n8.x4.shared.b16 {%0,%1,%2,%3}, [%4];"
        : "=r"(r[0]), "=r"(r[1]), "=r"(r[2]), "=r"(r[3]) : "r"(addr));
}
__device__ __forceinline__ void ldm_x4t(uint32_t addr, uint32_t* r) {
    asm volatile("ldmatrix.sync.aligned.m8n8.x4.trans.shared.b16 {%0,%1,%2,%3}, [%4];"
        : "=r"(r[0]), "=r"(r[1]), "=r"(r[2]), "=r"(r[3]) : "r"(addr));
}
__device__ __forceinline__ void mma_bf16(float* c, const uint32_t* a, const uint32_t* b) {
    asm volatile("mma.sync.aligned.m16n8k16.row.col.f32.bf16.bf16.f32 "
        "{%0,%1,%2,%3}, {%4,%5,%6,%7}, {%8,%9}, {%0,%1,%2,%3};"
        : "+f"(c[0]), "+f"(c[1]), "+f"(c[2]), "+f"(c[3])
        : "r"(a[0]), "r"(a[1]), "r"(a[2]), "r"(a[3]), "r"(b[0]), "r"(b[1]));
}
__device__ __forceinline__ int ctaOf(int t) {
    return t < 7 * EXTRA_T ? t / 7 : (t - EXTRA_T) / 6;
}

// 12 MMAs across 4 accumulator chains (spacing 4), per-chain order:
//   (a_hi,b_hi) -> (a_hi,b_lo) -> (a_lo,b_hi)   [numerically same as before]
__device__ __forceinline__ void mma12(float (*acc)[4],
                                      const uint32_t* ah, const uint32_t* al,
                                      const uint32_t* bh0, const uint32_t* bl0,
                                      const uint32_t* bh1, const uint32_t* bl1) {
    mma_bf16(acc[0], ah, bh0);     mma_bf16(acc[1], ah, bh0 + 2);
    mma_bf16(acc[2], ah, bh1);     mma_bf16(acc[3], ah, bh1 + 2);
    mma_bf16(acc[0], ah, bl0);     mma_bf16(acc[1], ah, bl0 + 2);
    mma_bf16(acc[2], ah, bl1);     mma_bf16(acc[3], ah, bl1 + 2);
    mma_bf16(acc[0], al, bh0);     mma_bf16(acc[1], al, bh0 + 2);
    mma_bf16(acc[2], al, bh1);     mma_bf16(acc[3], al, bh1 + 2);
}

// ---------------------------------------------------------------------------
__global__ __launch_bounds__(256, 2)
void vlad_main_mma(const float* __restrict__ x, const float* __restrict__ cent,
                   float* __restrict__ out) {
    extern __shared__ char sm[];
    const uint32_t smb = smem_u32(sm);
    float*  x2s  = (float*)(sm + SM_X2);
    float*  c2s  = (float*)(sm + SM_C2);
    float2* red2 = (float2*)(sm + SM_RED);
    __shared__ int   s_isLast;
    __shared__ float s_red[8];
    __shared__ float s_inv;

    const int tid  = threadIdx.x;
    const int w    = tid >> 5;
    const int lane = tid & 31;
    const int cta  = blockIdx.x;
    const int r4   = lane >> 2;
    const int q4   = lane & 3;
    const int ng   = w & 3;
    const int kh   = w >> 2;
    const int n0   = ng * 16;
    const int d0   = w * 16;
    const int q3   = tid & 3;
    const int r3   = tid >> 2;

    const int start = cta * BASE_T + (cta < EXTRA_T ? cta : EXTRA_T);
    const int cnt   = BASE_T + (cta < EXTRA_T ? 1 : 0);

    // ---- centroids -> CHI/CLO + c2 ----
    {
        const float4* c4 = (const float4*)cent;
        float csum = 0.f;
        char* rowp_h = sm + SM_CHI + r3 * XROW;
        #pragma unroll
        for (int it = 0; it < 8; ++it) {
            int f4 = q3 + it * 4;
            float4 v = c4[r3 * 32 + f4];
            csum += v.x * v.x + v.y * v.y + v.z * v.z + v.w * v.w;
            uint2 hw, lw;
            split2(v.x, v.y, hw.x, lw.x);
            split2(v.z, v.w, hw.y, lw.y);
            *(uint2*)(rowp_h + f4 * 8) = hw;
            *(uint2*)(rowp_h + (SM_CLO - SM_CHI) + f4 * 8) = lw;
        }
        csum += __shfl_xor_sync(0xffffffffu, csum, 1);
        csum += __shfl_xor_sync(0xffffffffu, csum, 2);
        if (q3 == 0) c2s[r3] = csum;
    }
    __syncthreads();

    float c2v[8];
    #pragma unroll
    for (int j = 0; j < 4; ++j) {
        c2v[2 * j]     = c2s[kh * 32 + j * 8 + q4 * 2];
        c2v[2 * j + 1] = c2s[kh * 32 + j * 8 + q4 * 2 + 1];
    }

    float acc2[8][4];
    #pragma unroll
    for (int j = 0; j < 8; ++j)
        #pragma unroll
        for (int c = 0; c < 4; ++c) acc2[j][c] = 0.f;
    float asum[8];
    #pragma unroll
    for (int i = 0; i < 8; ++i) asum[i] = 0.f;

    const uint32_t g1a  = smb + SM_XHI + (uint32_t)((n0 + (lane & 15)) * XROW
                         + (((lane >> 4) & 1) << 4));
    const uint32_t g1b4 = smb + SM_CHI + (uint32_t)((kh * 32 + (lane & 7)
                         + (((lane >> 4) & 1) << 3)) * XROW
                         + (((lane >> 3) & 1) << 4));
    const uint32_t g2a  = smb + SM_XHI + (uint32_t)(((((lane >> 4) & 1) << 3) + (lane & 7)) * XROW
                         + d0 * 2 + (((lane >> 3) & 1) << 4));
    const uint32_t g2b4 = smb + SM_AHI + (uint32_t)(((lane & 7) + (((lane >> 3) & 1) << 3)) * AROW
                         + (((lane >> 4) & 1) << 4));

    for (int it = 0; it < cnt; ++it) {
        const int t  = start + it;
        const int bt = t >> 6;

        // ---- L2 prefetch of next tile's x rows (no registers held) ----
        if (it + 1 < cnt) {
            const float4* nx = (const float4*)x + (size_t)((t + 1) * TILE_ + r3) * 32;
            #pragma unroll
            for (int i8 = 0; i8 < 8; ++i8)
                asm volatile("prefetch.global.L2 [%0];" :: "l"(nx + q3 + i8 * 4));
        }

        __syncthreads();   // previous tile's GEMM2 done with x / a-tiles

        // ---- load x tile -> XHI/XLO + x2 ----
        {
            const float4* xg = (const float4*)x + (size_t)(t * TILE_ + r3) * 32;
            char* rowp = sm + SM_XHI + r3 * XROW;
            float xsum = 0.f;
            #pragma unroll
            for (int i8 = 0; i8 < 8; ++i8) {
                int f4 = q3 + i8 * 4;
                float4 v = xg[f4];
                xsum += v.x * v.x + v.y * v.y + v.z * v.z + v.w * v.w;
                uint2 hw, lw;
                split2(v.x, v.y, hw.x, lw.x);
                split2(v.z, v.w, hw.y, lw.y);
                *(uint2*)(rowp + f4 * 8) = hw;
                *(uint2*)(rowp + (SM_XLO - SM_XHI) + f4 * 8) = lw;
            }
            xsum += __shfl_xor_sync(0xffffffffu, xsum, 1);
            xsum += __shfl_xor_sync(0xffffffffu, xsum, 2);
            if (q3 == 0) x2s[r3] = xsum;
        }
        __syncthreads();

        // ---- GEMM1: D1[16 n x 32 kc] = x.c^T, 4-way interleaved chains ----
        float acc1[4][4];
        #pragma unroll
        for (int j = 0; j < 4; ++j)
            #pragma unroll
            for (int c = 0; c < 4; ++c) acc1[j][c] = 0.f;

        #pragma unroll
        for (int ks = 0; ks < 8; ++ks) {
            uint32_t ah[4], al[4];
            ldm_x4(g1a + ks * 32, ah);
            ldm_x4(g1a + (SM_XLO - SM_XHI) + ks * 32, al);
            uint32_t bh0[4], bl0[4], bh1[4], bl1[4];
            ldm_x4(g1b4 + ks * 32, bh0);
            ldm_x4(g1b4 + (SM_CLO - SM_CHI) + ks * 32, bl0);
            ldm_x4(g1b4 + 16 * XROW + ks * 32, bh1);
            ldm_x4(g1b4 + (SM_CLO - SM_CHI) + 16 * XROW + ks * 32, bl1);
            mma12(acc1, ah, al, bh0, bl0, bh1, bl1);
        }

        // ---- softmax part 1: per-half logits, max, expsum ----
        const int pa = n0 + r4, pb = pa + 8;
        float lga[8], lgb[8];
        {
            const float xa = x2s[pa], xb = x2s[pb];
            float ma = -1e30f, mb = -1e30f;
            #pragma unroll
            for (int j = 0; j < 4; ++j) {
                #pragma unroll
                for (int c = 0; c < 2; ++c) {
                    float da = fmaxf(xa + c2v[2 * j + c] - 2.f * acc1[j][c],     1e-30f);
                    float db = fmaxf(xb + c2v[2 * j + c] - 2.f * acc1[j][2 + c], 1e-30f);
                    float la = -ALPHA_ * (da * rsqrtf(da));
                    float lb = -ALPHA_ * (db * rsqrtf(db));
                    lga[2 * j + c] = la; lgb[2 * j + c] = lb;
                    ma = fmaxf(ma, la);  mb = fmaxf(mb, lb);
                }
            }
            ma = fmaxf(ma, __shfl_xor_sync(0xffffffffu, ma, 1));
            ma = fmaxf(ma, __shfl_xor_sync(0xffffffffu, ma, 2));
            mb = fmaxf(mb, __shfl_xor_sync(0xffffffffu, mb, 1));
            mb = fmaxf(mb, __shfl_xor_sync(0xffffffffu, mb, 2));
            float sa = 0.f, sb = 0.f;
            #pragma unroll
            for (int i = 0; i < 8; ++i) {
                lga[i] = __expf(lga[i] - ma); sa += lga[i];
                lgb[i] = __expf(lgb[i] - mb); sb += lgb[i];
            }
            sa += __shfl_xor_sync(0xffffffffu, sa, 1);
            sa += __shfl_xor_sync(0xffffffffu, sa, 2);
            sb += __shfl_xor_sync(0xffffffffu, sb, 1);
            sb += __shfl_xor_sync(0xffffffffu, sb, 2);
            if (q4 == 0) {
                red2[kh * 64 + pa] = make_float2(ma, sa);
                red2[kh * 64 + pb] = make_float2(mb, sb);
            }
        }
        __syncthreads();

        // ---- softmax part 2: exact merge of the two halves, write a ----
        {
            float2 a0 = red2[pa], a1 = red2[64 + pa];
            float2 b0 = red2[pb], b1 = red2[64 + pb];
            float mA = fmaxf(a0.x, a1.x);
            float sA = a0.y * __expf(a0.x - mA) + a1.y * __expf(a1.x - mA);
            float scA = __expf((kh ? a1.x : a0.x) - mA) / sA;
            float mB = fmaxf(b0.x, b1.x);
            float sB = b0.y * __expf(b0.x - mB) + b1.y * __expf(b1.x - mB);
            float scB = __expf((kh ? b1.x : b0.x) - mB) / sB;

            char* aw_a = sm + SM_AHI + pa * AROW + kh * 64 + q4 * 4;
            char* aw_b = sm + SM_AHI + pb * AROW + kh * 64 + q4 * 4;
            #pragma unroll
            for (int j = 0; j < 4; ++j) {
                float va0 = lga[2 * j] * scA, va1 = lga[2 * j + 1] * scA;
                float vb0 = lgb[2 * j] * scB, vb1 = lgb[2 * j + 1] * scB;
                asum[2 * j]     += va0 + vb0;
                asum[2 * j + 1] += va1 + vb1;
                uint32_t hw, lw;
                split2(va0, va1, hw, lw);
                *(uint32_t*)(aw_a + j * 16) = hw;
                *(uint32_t*)(aw_a + (SM_ALO - SM_AHI) + j * 16) = lw;
                split2(vb0, vb1, hw, lw);
                *(uint32_t*)(aw_b + j * 16) = hw;
                *(uint32_t*)(aw_b + (SM_ALO - SM_AHI) + j * 16) = lw;
            }
        }
        __syncthreads();   // a-tiles visible to all warps

        // ---- GEMM2: D2[16 d x 64 kc] += xT.a, 4-way interleaved chains ----
        #pragma unroll
        for (int ns = 0; ns < 4; ++ns) {
            uint32_t ah[4], al[4];
            ldm_x4t(g2a + ns * (16 * XROW), ah);
            ldm_x4t(g2a + (SM_XLO - SM_XHI) + ns * (16 * XROW), al);
            #pragma unroll
            for (int jp = 0; jp < 2; ++jp) {
                uint32_t bh0[4], bl0[4], bh1[4], bl1[4];
                uint32_t ba = g2b4 + ns * (16 * AROW) + jp * 64;
                ldm_x4t(ba, bh0);
                ldm_x4t(ba + (SM_ALO - SM_AHI), bl0);
                ldm_x4t(ba + 32, bh1);
                ldm_x4t(ba + (SM_ALO - SM_AHI) + 32, bl1);
                mma12(&acc2[4 * jp], ah, al, bh0, bl0, bh1, bl1);
            }
        }

        // ---- flush on batch boundary / end, then maybe finalize ----
        const bool lastOfBatch = (it == cnt - 1) || (((t + 1) >> 6) != bt);
        if (lastOfBatch) {
            float* gv = g_vlad + bt * K_ * D_;
            const int dd = d0 + r4;
            #pragma unroll
            for (int j = 0; j < 8; ++j) {
                const int kc = j * 8 + q4 * 2;
                atomicAdd(&gv[kc * D_ + dd],           acc2[j][0]);
                atomicAdd(&gv[(kc + 1) * D_ + dd],     acc2[j][1]);
                atomicAdd(&gv[kc * D_ + dd + 8],       acc2[j][2]);
                atomicAdd(&gv[(kc + 1) * D_ + dd + 8], acc2[j][3]);
                acc2[j][0] = acc2[j][1] = acc2[j][2] = acc2[j][3] = 0.f;
            }
            #pragma unroll
            for (int i = 0; i < 8; ++i) {
                float v = asum[i];
                v += __shfl_xor_sync(0xffffffffu, v, 4);
                v += __shfl_xor_sync(0xffffffffu, v, 8);
                v += __shfl_xor_sync(0xffffffffu, v, 16);
                if (lane < 4)
                    atomicAdd(&g_asum[bt * K_ + kh * 32 + (i >> 1) * 8 + lane * 2 + (i & 1)], v);
                asum[i] = 0.f;
            }
            __threadfence();
            __syncthreads();
            if (tid == 0) {
                int nc = ctaOf(bt * 64 + 63) - ctaOf(bt * 64) + 1;
                s_isLast = (atomicAdd(&g_done[bt], 1) == nc - 1);
            }
            __syncthreads();
            if (s_isLast) {
                __threadfence();
                float vv[32], ssq = 0.f;
                #pragma unroll
                for (int m = 0; m < 32; ++m) {
                    const int e = m * 256 + tid;
                    const int k = e >> 7;
                    const int d = e & 127;
                    float val = fmaf(-g_asum[bt * K_ + k], cent[k * D_ + d],
                                     g_vlad[bt * K_ * D_ + e]);
                    vv[m] = val;
                    ssq = fmaf(val, val, ssq);
                }
                #pragma unroll
                for (int o = 16; o > 0; o >>= 1)
                    ssq += __shfl_xor_sync(0xffffffffu, ssq, o);
                if (lane == 0) s_red[w] = ssq;
                __syncthreads();
                if (tid == 0) {
                    float tot = 0.f;
                    #pragma unroll
                    for (int wv = 0; wv < 8; ++wv) tot += s_red[wv];
                    s_inv = 1.0f / fmaxf(sqrtf(tot), 1e-12f);
                }
                __syncthreads();
                const float inv = s_inv;
                #pragma unroll
                for (int m = 0; m < 32; ++m)
                    out[bt * K_ * D_ + m * 256 + tid] = vv[m] * inv;
            }
        }
    }
}

extern "C" void kernel_launch(void* const* d_in, const int* in_sizes, int n_in,
                              void* d_out, int out_size) {
    const float* x    = (const float*)d_in[0];   // [32,4096,128] f32
    const float* cent = (const float*)d_in[1];   // [64,128] f32
    float* out = (float*)d_out;                  // [32,8192] f32
    (void)in_sizes; (void)n_in; (void)out_size;

    cudaFuncSetAttribute(vlad_main_mma, cudaFuncAttributeMaxDynamicSharedMemorySize,
                         SMEM_BYTES);

    vlad_zero<<<(B_ * K_ * D_ + 255) / 256, 256>>>();
    vlad_main_mma<<<NCTA_, 256, SMEM_BYTES>>>(x, cent, out);
}